// round 14
// baseline (speedup 1.0000x reference)
#include <cuda_runtime.h>

// Static device scratch (no allocation allowed anywhere). Zero at module
// load; finalizers atomicExch used accum columns back to 0 and reset the
// counters, so each invocation (incl. graph replays) starts clean.
#define MAX_SEGS 8192
#define HMAX     2
#define QS       4                              // segments per group
#define LOG_EPS  (-27.631021115928547f)         // log(1e-12)

__device__ float g_accum[MAX_SEGS * 256];       // 8 MB
__device__ int   g_cnt[MAX_SEGS * HMAX];        // per (segment, col-half)

__device__ __forceinline__ int load_seg_id(const void* batch, int is64, int idx) {
    return is64 ? (int)((const long long*)batch)[idx]
                : ((const int*)batch)[idx];
}

// Sub-warp-collective lower_bound over W lanes (W = 16 or 32):
// smallest i in [0,n] with batch[i] >= target.
__device__ __forceinline__ int sub_lower_bound(const void* batch, int is64,
                                               int n, int target, int sublane,
                                               int W, unsigned mask, int base,
                                               unsigned wmask) {
    int lo = 0, hi = n;
    while (hi - lo > W) {
        int chunk = (hi - lo + W - 1) / W;
        int idx   = lo + sublane * chunk;
        bool lt   = false;
        if (idx < hi) lt = load_seg_id(batch, is64, idx) < target;
        unsigned bal = (__ballot_sync(mask, lt) >> base) & wmask;
        if (bal == 0) { hi = lo; break; }
        int l     = 31 - __clz(bal);
        int newlo = lo + l * chunk + 1;
        int newhi = lo + (l + 1) * chunk;
        hi = newhi < hi ? newhi : hi;
        lo = newlo;
    }
    if (hi <= lo) return lo;
    bool ge = false;
    int idx = lo + sublane;
    if (idx < hi) ge = load_seg_id(batch, is64, idx) >= target;
    unsigned bal = (__ballot_sync(mask, ge) >> base) & wmask;
    return bal ? (lo + __ffs(bal) - 1) : hi;
}

__device__ __forceinline__ void acc4(float4 v, float a[4]) {
    a[0] += __expf(v.x);
    a[1] += __expf(v.y);
    a[2] += __expf(v.z);
    a[3] += __expf(v.w);
}

// R11's streaming loop, verbatim: rows rs+rg, rs+rg+4, ... < re,
// 4-deep LDG.128 software prefetch.
__device__ __forceinline__ void stream_rows(const float4* __restrict__ f4,
                                            int rs, int re, int rg, int c4,
                                            size_t rstride,
                                            float s[4], float t[4]) {
    const float4* __restrict__ p = f4 + (size_t)(rs + rg) * rstride + c4;
    int r = rs + rg;
    if (r + 12 < re) {
        float4 a0 = __ldg(p);
        float4 a1 = __ldg(p +  4 * rstride);
        float4 a2 = __ldg(p +  8 * rstride);
        float4 a3 = __ldg(p + 12 * rstride);
        p += 16 * rstride;
        r += 16;
        for (; r + 12 < re; r += 16) {
            float4 b0 = __ldg(p);
            float4 b1 = __ldg(p +  4 * rstride);
            float4 b2 = __ldg(p +  8 * rstride);
            float4 b3 = __ldg(p + 12 * rstride);
            p += 16 * rstride;
            acc4(a0, s);
            acc4(a1, t);
            acc4(a2, s);
            acc4(a3, t);
            a0 = b0; a1 = b1; a2 = b2; a3 = b3;
        }
        acc4(a0, s);
        acc4(a1, t);
        acc4(a2, s);
        acc4(a3, t);
    }
    for (; r < re; r += 4) {
        float4 v = __ldg(p);
        p += 4 * rstride;
        acc4(v, s);
    }
}

// ---------------------------------------------------------------------------
// One block per (segment-group of 4, 128-col half, quarter z). 128 threads =
// 32 float4-lanes x 4 row-groups; 1024 blocks, 8/SM, single wave (as R11).
// The group's rows [b0,b4) are cut into 4 EQUAL quarters -> per-block work
// variance is 1/4 of per-segment variance, shrinking the latency-bound tail.
// Each quarter streams pure contiguous sub-loops per segment piece.
// ---------------------------------------------------------------------------
__global__ __launch_bounds__(128, 8)
void pool_lse_kernel(const float* __restrict__ feats,
                     const void* __restrict__ batch,
                     float* __restrict__ out,
                     int n, int D, int G) {
    __shared__ int   sh_is64;
    __shared__ int   sh_b[QS + 1];
    __shared__ float sm_s[4][128];
    __shared__ int   sh_old;

    const int lane = threadIdx.x & 31;
    const int rg   = threadIdx.x >> 5;

    // Dtype probe (warp 0): int64 values in [0,G) => odd 32-bit words are all
    // zero high-halves; any nonzero sampled odd word => int32.
    if (rg == 0) {
        const int* b32 = (const int*)batch;
        int limit = n < 8192 ? n : 8192;
        int step  = limit / 32; if (step < 2) step = 2;
        int idx   = lane * step + 1;
        if (idx >= limit) idx = limit - 1;
        idx |= 1;
        if (idx >= limit) idx -= 2;
        int v = (idx >= 0) ? b32[idx] : 0;
        unsigned nz = __ballot_sync(0xFFFFFFFFu, v != 0);
        if (lane == 0) sh_is64 = (nz == 0) ? 1 : 0;
    }
    __syncthreads();
    const int is64 = sh_is64;

    const int g0 = blockIdx.x * QS;

    // 5 boundary searches in ONE parallel round:
    //   warp 0 half-warps (16-ary): b[0] and b[QS];
    //   warps 1..3 (32-ary):        b[1..3].
    if (rg == 0) {
        int hw  = lane >> 4;
        int sub = lane & 15;
        int k   = hw ? QS : 0;
        int tgt = g0 + k; if (tgt > G) tgt = G;
        unsigned mask = hw ? 0xFFFF0000u : 0x0000FFFFu;
        int r = sub_lower_bound(batch, is64, n, tgt, sub, 16, mask,
                                hw * 16, 0xFFFFu);
        if (sub == 0) sh_b[k] = r;
    } else {
        int tgt = g0 + rg; if (tgt > G) tgt = G;
        int r = sub_lower_bound(batch, is64, n, tgt, lane, 32, 0xFFFFFFFFu,
                                0, 0xFFFFFFFFu);
        if (lane == 0) sh_b[rg] = r;
    }
    __syncthreads();

    const int b0 = sh_b[0];
    const int b4 = sh_b[QS];
    const int L  = b4 - b0;
    const int z  = blockIdx.z;
    const int q_lo = b0 + (z * L) / QS;
    const int q_hi = (z == QS - 1) ? b4 : b0 + ((z + 1) * L) / QS;

    const int h      = blockIdx.y;
    const int colblk = h * 128;
    const int c4     = (colblk >> 2) + lane;
    const size_t rstride = (size_t)(D >> 2);
    const float4* __restrict__ f4 = (const float4*)feats;
    const int c = threadIdx.x;                    // my output column in half

    for (int i = 0; i < QS; ++i) {
        const int gi = g0 + i;
        if (gi >= G) break;
        const int bi  = sh_b[i];
        const int bi1 = sh_b[i + 1];

        if (bi == bi1) {
            // Empty segment: deterministic owner quarter writes log(1e-12).
            int owner = QS - 1;
            for (int zz = 0; zz < QS - 1; ++zz) {
                int qe = b0 + ((zz + 1) * L) / QS;
                if (bi < qe) { owner = zz; break; }
            }
            if (z == owner)
                out[(size_t)gi * D + colblk + c] = LOG_EPS;
            continue;
        }

        const int ps = q_lo > bi  ? q_lo : bi;    // block-uniform
        const int pe = q_hi < bi1 ? q_hi : bi1;
        if (ps >= pe) continue;

        // Contributor count for this (segment): identical in all blocks.
        int E = 0;
#pragma unroll
        for (int zz = 0; zz < QS; ++zz) {
            int qa = b0 + (zz * L) / QS;
            int qb = (zz == QS - 1) ? b4 : b0 + ((zz + 1) * L) / QS;
            int a = qa > bi  ? qa : bi;
            int d = qb < bi1 ? qb : bi1;
            if (a < d) E++;
        }

        float s[4] = {0.f, 0.f, 0.f, 0.f};
        float t[4] = {0.f, 0.f, 0.f, 0.f};
        stream_rows(f4, ps, pe, rg, c4, rstride, s, t);

        __syncthreads();                          // sm_s reuse (WAR)
#pragma unroll
        for (int j = 0; j < 4; ++j)
            sm_s[rg][lane * 4 + j] = s[j] + t[j];
        __syncthreads();

        float S = sm_s[0][c] + sm_s[1][c] + sm_s[2][c] + sm_s[3][c];

        if (E == 1) {
            // Sole contributor: direct store, no atomics.
            out[(size_t)gi * D + colblk + c] = __logf(fmaxf(S, 1e-12f));
        } else {
            atomicAdd(&g_accum[(size_t)gi * D + colblk + c], S);
            __threadfence();                      // release before counting
            __syncthreads();
            if (threadIdx.x == 0)
                sh_old = atomicAdd(&g_cnt[gi * HMAX + h], 1);
            __syncthreads();
            if (sh_old == E - 1) {                // last contributor finalizes
                __threadfence();                  // acquire all adds
                float v = atomicExch(&g_accum[(size_t)gi * D + colblk + c], 0.0f);
                out[(size_t)gi * D + colblk + c] = __logf(fmaxf(v, 1e-12f));
                if (threadIdx.x == 0)
                    atomicExch(&g_cnt[gi * HMAX + h], 0);
            }
        }
    }
}

// ---------------------------------------------------------------------------
// Inputs (metadata order): feats f32 [N*D], batch int [N], num_segments.
// ---------------------------------------------------------------------------
extern "C" void kernel_launch(void* const* d_in, const int* in_sizes, int n_in,
                              void* d_out, int out_size) {
    const float* feats = (const float*)d_in[0];
    const void*  batch = d_in[1];

    const int n = in_sizes[1];                 // rows (200000)
    const int D = in_sizes[0] / n;             // features (256)
    const int G = out_size / D;                // segments (512)
    const int H = D / 128;                     // column halves (2)

    dim3 grid((G + QS - 1) / QS, H, QS);       // 128 x 2 x 4 = 1024 blocks
    pool_lse_kernel<<<grid, 128>>>(feats, batch, (float*)d_out, n, D, G);
}

// round 15
// speedup vs baseline: 1.1497x; 1.1497x over previous
#include <cuda_runtime.h>

// ---------------------------------------------------------------------------
// Base = R11 (best measured: 38.98 us), with two in-loop micro-changes:
//  1) explicit role-swap double buffer (no a=b MOVs -> no scoreboard coupling
//     between consuming the current batch and issuing the next loads)
//  2) __ldcs streaming loads on feats (read-once data, evict-first in L2)
// Everything else byte-identical to R11.
// ---------------------------------------------------------------------------

__device__ __forceinline__ int load_seg(const void* batch, int is64, int idx) {
    return is64 ? (int)((const long long*)batch)[idx]
                : ((const int*)batch)[idx];
}

// Warp-collective lower_bound: smallest i in [0,n] with batch[i] >= target.
__device__ __forceinline__ int warp_lower_bound(const void* batch, int is64,
                                                int n, int target, int lane) {
    int lo = 0, hi = n;
    while (hi - lo > 32) {
        int chunk = (hi - lo + 31) >> 5;          // ceil(range/32)
        int idx   = lo + lane * chunk;
        bool lt   = false;
        if (idx < hi) lt = load_seg(batch, is64, idx) < target;
        unsigned bal = __ballot_sync(0xFFFFFFFFu, lt);
        if (bal == 0) { hi = lo; break; }
        int l     = 31 - __clz(bal);
        int newlo = lo + l * chunk + 1;
        int newhi = lo + (l + 1) * chunk;
        hi = newhi < hi ? newhi : hi;
        lo = newlo;
    }
    if (hi <= lo) return lo;
    bool ge = false;
    int idx = lo + lane;
    if (idx < hi) ge = load_seg(batch, is64, idx) >= target;
    unsigned bal = __ballot_sync(0xFFFFFFFFu, ge);
    return bal ? (lo + __ffs(bal) - 1) : hi;
}

__device__ __forceinline__ void acc4(float4 v, float a[4]) {
    a[0] += __expf(v.x);
    a[1] += __expf(v.y);
    a[2] += __expf(v.z);
    a[3] += __expf(v.w);
}

__global__ __launch_bounds__(128, 8)
void pool_lse_kernel(const float* __restrict__ feats,
                     const void* __restrict__ batch,
                     float* __restrict__ out,
                     int n, int D, int G) {
    __shared__ int sh_is64;
    __shared__ int sh_bounds[2];

    const int lane = threadIdx.x & 31;
    const int rg   = threadIdx.x >> 5;            // warp / row-group 0..3

    // Dtype probe (warp 0): int64 values in [0,G) => odd 32-bit words are all
    // zero high-halves; any nonzero sampled odd word => int32.
    if (rg == 0) {
        const int* b32 = (const int*)batch;
        int limit = n < 8192 ? n : 8192;
        int step  = limit / 32; if (step < 2) step = 2;
        int idx   = lane * step + 1;
        if (idx >= limit) idx = limit - 1;
        idx |= 1;
        if (idx >= limit) idx -= 2;
        int v = (idx >= 0) ? b32[idx] : 0;
        unsigned nz = __ballot_sync(0xFFFFFFFFu, v != 0);
        if (lane == 0) sh_is64 = (nz == 0) ? 1 : 0;
    }
    __syncthreads();
    const int is64 = sh_is64;

    const int g = blockIdx.x;

    // Warps 0/1: lower_bound(g) / lower_bound(g+1), ~5 L2-resident loads.
    if (rg < 2) {
        int r = warp_lower_bound(batch, is64, n, g + rg, lane);
        if (lane == 0) sh_bounds[rg] = r;
    }
    __syncthreads();

    int start = sh_bounds[0];
    int end   = sh_bounds[1];

    const int colblk = blockIdx.y * 128;
    const int c4     = (colblk >> 2) + lane;

    float s[4] = {0.f, 0.f, 0.f, 0.f};
    float t[4] = {0.f, 0.f, 0.f, 0.f};

    const size_t rstride = (size_t)(D >> 2);      // float4s per row
    const float4* __restrict__ p =
        (const float4*)feats + (size_t)(start + rg) * rstride + c4;

    int r = start + rg;                           // rows: r, r+4, r+8, ...
    if (r + 12 < end) {
        // Prologue: 4 in-flight streaming LDG.128.
        float4 a0 = __ldcs(p);
        float4 a1 = __ldcs(p +  4 * rstride);
        float4 a2 = __ldcs(p +  8 * rstride);
        float4 a3 = __ldcs(p + 12 * rstride);
        p += 16 * rstride;
        r += 16;
        // Steady state: explicit role swap, no register moves. Loads for the
        // next phase always issue BEFORE consuming the current batch.
        for (;;) {
            // phase A: load into b, consume a
            if (r + 12 >= end) {
                acc4(a0, s); acc4(a1, t); acc4(a2, s); acc4(a3, t);
                break;
            }
            float4 b0 = __ldcs(p);
            float4 b1 = __ldcs(p +  4 * rstride);
            float4 b2 = __ldcs(p +  8 * rstride);
            float4 b3 = __ldcs(p + 12 * rstride);
            p += 16 * rstride;
            r += 16;
            acc4(a0, s); acc4(a1, t); acc4(a2, s); acc4(a3, t);

            // phase B: load into a, consume b
            if (r + 12 >= end) {
                acc4(b0, s); acc4(b1, t); acc4(b2, s); acc4(b3, t);
                break;
            }
            a0 = __ldcs(p);
            a1 = __ldcs(p +  4 * rstride);
            a2 = __ldcs(p +  8 * rstride);
            a3 = __ldcs(p + 12 * rstride);
            p += 16 * rstride;
            r += 16;
            acc4(b0, s); acc4(b1, t); acc4(b2, s); acc4(b3, t);
        }
    }
    for (; r < end; r += 4) {
        float4 v = __ldcs(p);
        p += 4 * rstride;
        acc4(v, s);
    }

    // ---- merge 4 row-group partials per column through shared memory ----
    __shared__ float sm_s[4][128];
#pragma unroll
    for (int j = 0; j < 4; ++j) {
        sm_s[rg][lane * 4 + j] = s[j] + t[j];
    }
    __syncthreads();

    {
        const int c = threadIdx.x;                // 128 threads = 128 columns
        float out_val;
        if (start >= end) {
            out_val = -27.631021115928547f;       // log(1e-12): empty segment
        } else {
            float S = sm_s[0][c] + sm_s[1][c] + sm_s[2][c] + sm_s[3][c];
            out_val = __logf(S);                  // S >= 2.5e-3*count >> 1e-12
        }
        out[(size_t)g * D + colblk + c] = out_val;
    }
}

// ---------------------------------------------------------------------------
// Inputs (metadata order): feats f32 [N*D], batch int [N], num_segments.
// ---------------------------------------------------------------------------
extern "C" void kernel_launch(void* const* d_in, const int* in_sizes, int n_in,
                              void* d_out, int out_size) {
    const float* feats = (const float*)d_in[0];
    const void*  batch = d_in[1];

    const int n = in_sizes[1];                // rows (200000)
    const int D = in_sizes[0] / n;            // features (256)
    const int G = out_size / D;               // segments (512)

    dim3 grid(G, D / 128);
    pool_lse_kernel<<<grid, 128>>>(feats, batch, (float*)d_out, n, D, G);
}